// round 11
// baseline (speedup 1.0000x reference)
#include <cuda_runtime.h>
#include <cuda_bf16.h>
#include <math.h>
#include <cstdint>

// Problem constants
#define B_  2
#define T_  2048
#define E_  2048
#define H_  16
#define KVH_ 8
#define D_  128
#define ROWS_ (B_ * T_)            // 4096
#define QKVN (H_ * D_ + 2 * KVH_ * D_)   // 4096 fused N
#define VOFF (H_ * D_ + KVH_ * D_)       // 3072: v column offset in fused buffer

// k-permutation within each 8-block: pos(c) = c<4 ? 2c : 2(c-4)+1
// (dot products invariant when BOTH GEMM operands share it)
#define KPERM(k) (((k) & ~7) | ((((k) & 4) >> 2) + 2 * ((k) & 3)))

// ---------------- scratch (device globals; no allocs allowed) ----------------
__device__ float g_qkv[(size_t)ROWS_ * QKVN];      // fused q|k|v (unpermuted)
__device__ float g_o[(size_t)ROWS_ * H_ * D_];     // attn out (k-permuted cols)
__device__ float g_xr[(size_t)ROWS_ * E_];         // tf32 x, k-permuted cols
__device__ float g_wqkvt[(size_t)QKVN * E_];       // [wq|wk|wv]^T, k-permuted
__device__ float g_wot[(size_t)E_ * H_ * D_];      // wo^T, k-permuted

// ====================== helpers ======================
__device__ __forceinline__ uint32_t smem_u32(const void* p) {
    uint32_t a;
    asm("{ .reg .u64 t; cvta.to.shared.u64 t, %1; cvt.u32.u64 %0, t; }" : "=r"(a) : "l"(p));
    return a;
}
#define CP_ASYNC16(dst, src) \
    asm volatile("cp.async.cg.shared.global [%0], [%1], 16;" :: "r"(dst), "l"(src))
#define CP_COMMIT() asm volatile("cp.async.commit_group;" ::: "memory")
#define CP_WAIT(n)  asm volatile("cp.async.wait_group %0;" :: "n"(n) : "memory")

__device__ __forceinline__ uint32_t f2tf32(float x) {
    uint32_t u;
    asm("cvt.rna.tf32.f32 %0, %1;" : "=r"(u) : "f"(x));
    return u;
}
__device__ __forceinline__ float tf32r(float x) {
    return __uint_as_float(f2tf32(x));
}
__device__ __forceinline__ void mma_tf32(float (&c)[4], const uint32_t (&a)[4],
                                         const uint32_t (&b)[2]) {
    asm volatile(
        "mma.sync.aligned.m16n8k8.row.col.f32.tf32.tf32.f32 "
        "{%0,%1,%2,%3}, {%4,%5,%6,%7}, {%8,%9}, {%0,%1,%2,%3};"
        : "+f"(c[0]), "+f"(c[1]), "+f"(c[2]), "+f"(c[3])
        : "r"(a[0]), "r"(a[1]), "r"(a[2]), "r"(a[3]), "r"(b[0]), "r"(b[1]));
}

// ============== round x to tf32, write k-permuted ==============
// Row stride E_ is a multiple of 8, so the flat-index 8-block == row 8-block.
__global__ void round_tf32_kernel(const float* __restrict__ in, float* __restrict__ out,
                                  int n4)
{
    int i = blockIdx.x * blockDim.x + threadIdx.x;
    if (i >= n4) return;
    float4 t = ((const float4*)in)[i];
    int f0 = i * 4;
    int base = f0 & ~7;             // 8-block base (global)
    int half = (f0 & 4) >> 2;       // 0: cols 0-3 of block, 1: cols 4-7
    out[base + half + 0] = tf32r(t.x);
    out[base + half + 2] = tf32r(t.y);
    out[base + half + 4] = tf32r(t.z);
    out[base + half + 6] = tf32r(t.w);
}

// ============== round v-slice of fused qkv buffer to tf32 (in place) ==========
__global__ void vround_kernel(float* __restrict__ X)
{
    int idx = blockIdx.x * blockDim.x + threadIdx.x;
    int row = idx >> 8, c4 = idx & 255;
    float4* p = (float4*)(X + (size_t)row * QKVN + VOFF) + c4;
    float4 t = *p;
    t.x = tf32r(t.x); t.y = tf32r(t.y); t.z = tf32r(t.z); t.w = tf32r(t.w);
    *p = t;
}

// ============ fused qkv weight transpose (k-permuted output) ============
__global__ void transpose_qkv_kernel(const float* __restrict__ Wq,
                                     const float* __restrict__ Wk,
                                     const float* __restrict__ Wv,
                                     float* __restrict__ Wt)
{
    __shared__ float tile[32][33];
    int z = blockIdx.z;
    const float* W = (z == 0) ? Wq : (z == 1) ? Wk : Wv;
    int N = (z == 0) ? (H_ * D_) : (KVH_ * D_);
    int rowoff = (z == 0) ? 0 : (z == 1) ? (H_ * D_) : (H_ * D_ + KVH_ * D_);
    int bx = blockIdx.x * 32;  // n (uniform per block)
    if (bx >= N) return;
    int by = blockIdx.y * 32;  // k
    int tx = threadIdx.x, ty = threadIdx.y;
#pragma unroll
    for (int j = 0; j < 32; j += 8)
        tile[ty + j][tx] = W[(size_t)(by + ty + j) * N + bx + tx];
    __syncthreads();
    int kp = KPERM(by + tx);
#pragma unroll
    for (int j = 0; j < 32; j += 8)
        Wt[(size_t)(rowoff + bx + ty + j) * E_ + kp] = tf32r(tile[tx][ty + j]);
}

// ============ wo transpose (k-permuted output) ==========
__global__ void transpose_kernel(const float* __restrict__ W, float* __restrict__ Wt,
                                 int K, int N)
{
    __shared__ float tile[32][33];
    int bx = blockIdx.x * 32;  // n
    int by = blockIdx.y * 32;  // k
    int tx = threadIdx.x, ty = threadIdx.y;
#pragma unroll
    for (int j = 0; j < 32; j += 8)
        tile[ty + j][tx] = W[(size_t)(by + ty + j) * N + bx + tx];
    __syncthreads();
    int kp = KPERM(by + tx);
#pragma unroll
    for (int j = 0; j < 32; j += 8)
        Wt[(size_t)(bx + ty + j) * K + kp] = tf32r(tile[tx][ty + j]);
}

// ====================== tf32 mma.sync GEMM (k-permuted operands) ==============
// C[M,N] = A[M,K] @ Bt[N,K]^T. CTA 128x128, BK=32, 2-stage cp.async, 2 CTAs/SM.
// Fragment gathers are paired LDS.64 thanks to the k-interleave.
#define GBM 128
#define GBN 128
#define GBK 32
#define GSTRIDE 36
#define GSTAGE_FLOATS (2 * GBM * GSTRIDE)
#define GSTAGES 2
#define GSMEM_BYTES (GSTAGES * GSTAGE_FLOATS * 4)   // 73728

__global__ void __launch_bounds__(256, 2) tc_gemm_kernel(
    int M, int N, int K,
    const float* __restrict__ A, const float* __restrict__ Bt,
    float* __restrict__ C)
{
    extern __shared__ float smf[];
    const uint32_t smem_base = smem_u32(smf);
    const int tid = threadIdx.x;
    const int wid = tid >> 5, lid = tid & 31;
    const int g = lid >> 2, tig = lid & 3;

    const int m0 = blockIdx.y * GBM;
    const int n0 = blockIdx.x * GBN;
    const float* Ab = A  + (size_t)m0 * K;
    const float* Bb = Bt + (size_t)n0 * K;
    const int nchunks = K / GBK;

    const int wm0 = (wid >> 2) * 64;
    const int wn0 = (wid & 3) * 32;

    float acc[16][4];
#pragma unroll
    for (int i = 0; i < 16; i++)
#pragma unroll
        for (int jj = 0; jj < 4; jj++) acc[i][jj] = 0.f;

    auto load_chunk = [&](int j) {
        const int stage = j & 1;
        const uint32_t abase = smem_base + stage * GSTAGE_FLOATS * 4;
        const uint32_t bbase = abase + GBM * GSTRIDE * 4;
        const float* ag = Ab + j * GBK;
        const float* bg = Bb + j * GBK;
#pragma unroll
        for (int i = 0; i < 4; i++) {
            int f = i * 256 + tid;
            int row = f >> 3, c = f & 7;
            uint32_t soff = (uint32_t)(row * GSTRIDE + c * 4) * 4;
            CP_ASYNC16(abase + soff, ag + (size_t)row * K + c * 4);
            CP_ASYNC16(bbase + soff, bg + (size_t)row * K + c * 4);
        }
    };

    load_chunk(0);
    CP_COMMIT();

    for (int j = 0; j < nchunks; j++) {
        CP_WAIT(0);
        __syncthreads();
        if (j + 1 < nchunks) { load_chunk(j + 1); CP_COMMIT(); }

        const float* as = smf + (j & 1) * GSTAGE_FLOATS;
        const float* bs = as + GBM * GSTRIDE;

#pragma unroll
        for (int ks = 0; ks < 4; ks++) {
            const int k0 = ks * 8;
            uint32_t afr[4][4], bfr[4][2];
#pragma unroll
            for (int mt = 0; mt < 4; mt++) {
                const float* ap = as + (wm0 + mt * 16 + g) * GSTRIDE + k0 + 2 * tig;
                float2 lo = *(const float2*)ap;                 // a0, a2
                float2 hi = *(const float2*)(ap + 8 * GSTRIDE); // a1, a3
                afr[mt][0] = __float_as_uint(lo.x);
                afr[mt][1] = __float_as_uint(hi.x);
                afr[mt][2] = __float_as_uint(lo.y);
                afr[mt][3] = __float_as_uint(hi.y);
            }
#pragma unroll
            for (int nt = 0; nt < 4; nt++) {
                float2 bb = *(const float2*)(bs + (wn0 + nt * 8 + g) * GSTRIDE + k0 + 2 * tig);
                bfr[nt][0] = __float_as_uint(bb.x);
                bfr[nt][1] = __float_as_uint(bb.y);
            }
#pragma unroll
            for (int mt = 0; mt < 4; mt++)
#pragma unroll
                for (int nt = 0; nt < 4; nt++)
                    mma_tf32(acc[mt * 4 + nt], afr[mt], bfr[nt]);
        }
        __syncthreads();
    }

#pragma unroll
    for (int mt = 0; mt < 4; mt++) {
#pragma unroll
        for (int nt = 0; nt < 4; nt++) {
            int row = m0 + wm0 + mt * 16 + g;
            int col = n0 + wn0 + nt * 8 + tig * 2;
            float2 lo = { acc[mt * 4 + nt][0], acc[mt * 4 + nt][1] };
            float2 hi = { acc[mt * 4 + nt][2], acc[mt * 4 + nt][3] };
            *(float2*)(C + (size_t)row * N + col) = lo;
            *(float2*)(C + (size_t)(row + 8) * N + col) = hi;
        }
    }
}

// ---------------- RoPE on a column-slice of the fused qkv buffer ------------
__global__ void rope_kernel(float* __restrict__ X, int rowstride, int coloff,
                            int nh, int total)
{
    int idx = blockIdx.x * blockDim.x + threadIdx.x;
    if (idx >= total) return;
    int j = idx & 63;
    int rest = idx >> 6;
    int hh = rest % nh;
    int row = rest / nh;
    int t = row & (T_ - 1);

    float inv = 1.0f / powf(10000.0f, (float)j * (1.0f / 64.0f));
    float ang = (float)t * inv;
    float s, c;
    sincosf(ang, &s, &c);

    float* p = X + (size_t)row * rowstride + coloff + hh * D_ + 2 * j;
    float x0 = p[0], x1 = p[1];
    p[0] = tf32r(x0 * c - x1 * s);
    p[1] = tf32r(x0 * s + x1 * c);
}

// ---------------- Flash attention (causal, GQA), Br=128, warp-private -------
// grid (T/128, H, B). Internals unchanged; epilogue writes O with k-permuted
// columns (consumed by the out-projection GEMM).
#define FSTR 132
#define F_QS 0
#define F_KS (128 * FSTR)
#define F_VS (F_KS + 2 * 64 * FSTR)
#define FLASH_SMEM_FLOATS (F_VS + 2 * 64 * FSTR)   // 50688 -> 202752 B

__global__ void __launch_bounds__(256, 1) flash_attn_kernel(
    const float* __restrict__ QKV, float* __restrict__ O)
{
    extern __shared__ float sm[];
    float* Qs = sm + F_QS;
    float* Ks0 = sm + F_KS;
    float* Vs0 = sm + F_VS;
    const uint32_t smem_base = smem_u32(sm);

    const int tid = threadIdx.x;
    const int wid = tid >> 5, lid = tid & 31;
    const int g = lid >> 2, tig = lid & 3;
    const int qt = gridDim.x - 1 - blockIdx.x;
    const int h = blockIdx.y, b = blockIdx.z;
    const int kvh = h >> 1;
    const int q0 = qt * 128;
    const int wr = wid * 16;

    const float* Qg = QKV + (size_t)h * D_;
    const float* Kq = QKV + H_ * D_ + (size_t)kvh * D_;
    const float* Vq = QKV + VOFF + (size_t)kvh * D_;

    auto prefetch_kv = [&](int kt) {
        const int stage = kt & 1;
        const uint32_t kb = smem_base + (uint32_t)(F_KS + stage * 64 * FSTR) * 4;
        const uint32_t vb = smem_base + (uint32_t)(F_VS + stage * 64 * FSTR) * 4;
#pragma unroll
        for (int i = 0; i < 8; i++) {
            int f = i * 256 + tid;
            int row = f >> 5, c16 = f & 31;
            size_t goff = (size_t)(b * T_ + kt * 64 + row) * QKVN + c16 * 4;
            uint32_t soff = (uint32_t)(row * FSTR + c16 * 4) * 4;
            CP_ASYNC16(kb + soff, Kq + goff);
            CP_ASYNC16(vb + soff, Vq + goff);
        }
    };

    {
#pragma unroll
        for (int i = 0; i < 16; i++) {
            int f = i * 256 + tid;
            int row = f >> 5, c = f & 31;
            const float4* src = (const float4*)(Qg + (size_t)(b * T_ + q0 + row) * QKVN) + c;
            *((float4*)(Qs + row * FSTR) + c) = *src;
        }
    }

    prefetch_kv(0);
    CP_COMMIT();

    float oacc[16][4];
#pragma unroll
    for (int i = 0; i < 16; i++)
#pragma unroll
        for (int jj = 0; jj < 4; jj++) oacc[i][jj] = 0.f;
    float m0 = -INFINITY, m1 = -INFINITY, l0 = 0.f, l1 = 0.f;

    const float scale = 0.08838834764831845f;
    const int last = 2 * qt + 1;
    const int srcA = (lid & ~3) | (tig >> 1);
    const int srcB = (lid & ~3) | (2 + (tig >> 1));
    const bool selb = (tig & 1);

    for (int kt = 0; kt <= last; kt++) {
        CP_WAIT(0);
        __syncthreads();
        if (kt < last) { prefetch_kv(kt + 1); CP_COMMIT(); }

        const float* ks = Ks0 + (kt & 1) * 64 * FSTR;
        const float* vs = Vs0 + (kt & 1) * 64 * FSTR;

        float sacc[8][4];
#pragma unroll
        for (int nt = 0; nt < 8; nt++)
#pragma unroll
            for (int jj = 0; jj < 4; jj++) sacc[nt][jj] = 0.f;

#pragma unroll
        for (int ksi = 0; ksi < 16; ksi++) {
            const int k0 = ksi * 8;
            uint32_t a[4];
            const uint32_t* ap = (const uint32_t*)(Qs + (wr + g) * FSTR + k0 + tig);
            a[0] = ap[0];
            a[1] = ap[8 * FSTR];
            a[2] = ap[4];
            a[3] = ap[8 * FSTR + 4];
#pragma unroll
            for (int nt = 0; nt < 8; nt++) {
                uint32_t bb[2];
                const uint32_t* bp = (const uint32_t*)(ks + (nt * 8 + g) * FSTR + k0 + tig);
                bb[0] = bp[0];
                bb[1] = bp[4];
                mma_tf32(sacc[nt], a, bb);
            }
        }

        {
            const int r0 = wr + g, r1 = wr + g + 8;
            const int koff = (kt - 2 * qt) * 64;
            const bool diag = (kt >= 2 * qt);
#pragma unroll
            for (int nt = 0; nt < 8; nt++) {
                int j0 = nt * 8 + 2 * tig;
                sacc[nt][0] *= scale;
                sacc[nt][1] *= scale;
                sacc[nt][2] *= scale;
                sacc[nt][3] *= scale;
                if (diag) {
                    if (koff + j0     > r0) sacc[nt][0] = -1e30f;
                    if (koff + j0 + 1 > r0) sacc[nt][1] = -1e30f;
                    if (koff + j0     > r1) sacc[nt][2] = -1e30f;
                    if (koff + j0 + 1 > r1) sacc[nt][3] = -1e30f;
                }
            }
        }

        {
            float mx0 = -INFINITY, mx1 = -INFINITY;
#pragma unroll
            for (int nt = 0; nt < 8; nt++) {
                mx0 = fmaxf(mx0, fmaxf(sacc[nt][0], sacc[nt][1]));
                mx1 = fmaxf(mx1, fmaxf(sacc[nt][2], sacc[nt][3]));
            }
            mx0 = fmaxf(mx0, __shfl_xor_sync(0xFFFFFFFF, mx0, 1));
            mx0 = fmaxf(mx0, __shfl_xor_sync(0xFFFFFFFF, mx0, 2));
            mx1 = fmaxf(mx1, __shfl_xor_sync(0xFFFFFFFF, mx1, 1));
            mx1 = fmaxf(mx1, __shfl_xor_sync(0xFFFFFFFF, mx1, 2));
            mx0 = fmaxf(mx0, m0);
            mx1 = fmaxf(mx1, m1);
            float sum0 = 0.f, sum1 = 0.f;
#pragma unroll
            for (int nt = 0; nt < 8; nt++) {
                float p0 = tf32r(__expf(sacc[nt][0] - mx0));
                float p1 = tf32r(__expf(sacc[nt][1] - mx0));
                float p2 = tf32r(__expf(sacc[nt][2] - mx1));
                float p3 = tf32r(__expf(sacc[nt][3] - mx1));
                sacc[nt][0] = p0; sacc[nt][1] = p1;
                sacc[nt][2] = p2; sacc[nt][3] = p3;
                sum0 += p0 + p1;
                sum1 += p2 + p3;
            }
            sum0 += __shfl_xor_sync(0xFFFFFFFF, sum0, 1);
            sum0 += __shfl_xor_sync(0xFFFFFFFF, sum0, 2);
            sum1 += __shfl_xor_sync(0xFFFFFFFF, sum1, 1);
            sum1 += __shfl_xor_sync(0xFFFFFFFF, sum1, 2);
            float al0 = __expf(m0 - mx0);
            float al1 = __expf(m1 - mx1);
            l0 = l0 * al0 + sum0;
            l1 = l1 * al1 + sum1;
            m0 = mx0; m1 = mx1;
#pragma unroll
            for (int nt = 0; nt < 16; nt++) {
                oacc[nt][0] *= al0; oacc[nt][1] *= al0;
                oacc[nt][2] *= al1; oacc[nt][3] *= al1;
            }
        }

#pragma unroll
        for (int ksi = 0; ksi < 8; ksi++) {
            const int k0 = ksi * 8;
            uint32_t a[4];
            {
                float v00 = __shfl_sync(0xFFFFFFFF, sacc[ksi][0], srcA);
                float v01 = __shfl_sync(0xFFFFFFFF, sacc[ksi][1], srcA);
                float v10 = __shfl_sync(0xFFFFFFFF, sacc[ksi][2], srcA);
                float v11 = __shfl_sync(0xFFFFFFFF, sacc[ksi][3], srcA);
                float w00 = __shfl_sync(0xFFFFFFFF, sacc[ksi][0], srcB);
                float w01 = __shfl_sync(0xFFFFFFFF, sacc[ksi][1], srcB);
                float w10 = __shfl_sync(0xFFFFFFFF, sacc[ksi][2], srcB);
                float w11 = __shfl_sync(0xFFFFFFFF, sacc[ksi][3], srcB);
                a[0] = __float_as_uint(selb ? v01 : v00);
                a[1] = __float_as_uint(selb ? v11 : v10);
                a[2] = __float_as_uint(selb ? w01 : w00);
                a[3] = __float_as_uint(selb ? w11 : w10);
            }
            const uint32_t* vp = (const uint32_t*)(vs + (k0 + tig) * FSTR);
#pragma unroll
            for (int nt = 0; nt < 16; nt++) {
                int col = nt * 8 + g;
                uint32_t bb[2];
                bb[0] = vp[col];
                bb[1] = vp[4 * FSTR + col];
                mma_tf32(oacc[nt], a, bb);
            }
        }
    }

    // epilogue: normalize, tf32-round, store with k-permuted columns.
    // within-block cols (2tig, 2tig+1) -> positions (p0, p0+2),
    // p0 = tig<2 ? 4tig : 4tig-7.
    {
        float il0 = 1.f / l0;
        float il1 = 1.f / l1;
        const int p0 = (tig < 2) ? 4 * tig : 4 * tig - 7;
        float* O0 = O + (size_t)(b * T_ + q0 + wr + g) * (H_ * D_) + h * D_;
        float* O1 = O + (size_t)(b * T_ + q0 + wr + g + 8) * (H_ * D_) + h * D_;
#pragma unroll
        for (int nt = 0; nt < 16; nt++) {
            int base = nt * 8;
            O0[base + p0]     = tf32r(oacc[nt][0] * il0);
            O0[base + p0 + 2] = tf32r(oacc[nt][1] * il0);
            O1[base + p0]     = tf32r(oacc[nt][2] * il1);
            O1[base + p0 + 2] = tf32r(oacc[nt][3] * il1);
        }
    }
}

// -------------------------------- launch -------------------------------------
extern "C" void kernel_launch(void* const* d_in, const int* in_sizes, int n_in,
                              void* d_out, int out_size)
{
    const float* x  = (const float*)d_in[0];
    const float* wq = (const float*)d_in[2];
    const float* wk = (const float*)d_in[3];
    const float* wv = (const float*)d_in[4];
    const float* wo = (const float*)d_in[5];
    float* out = (float*)d_out;

    float *qkv, *o, *xr, *wqkvt, *wot;
    cudaGetSymbolAddress((void**)&qkv, g_qkv);
    cudaGetSymbolAddress((void**)&o, g_o);
    cudaGetSymbolAddress((void**)&xr, g_xr);
    cudaGetSymbolAddress((void**)&wqkvt, g_wqkvt);
    cudaGetSymbolAddress((void**)&wot, g_wot);

    dim3 tb(32, 8);
    // launch 0: round x (k-permuted)
    round_tf32_kernel<<<(ROWS_ * E_ / 4 + 255) / 256, 256>>>(x, xr, ROWS_ * E_ / 4);
    // launch 1: fused qkv weight transpose (k-permuted)
    transpose_qkv_kernel<<<dim3(64, 64, 3), tb>>>(wq, wk, wv, wqkvt);
    // launch 2: wo transpose (k-permuted)
    transpose_kernel<<<dim3(E_ / 32, (H_ * D_) / 32), tb>>>(wo, wot, H_ * D_, E_);

    cudaFuncSetAttribute(tc_gemm_kernel,
                         cudaFuncAttributeMaxDynamicSharedMemorySize, GSMEM_BYTES);

    // launch 3 (ncu-captured): fused QKV projection
    tc_gemm_kernel<<<dim3(QKVN / 128, ROWS_ / 128), 256, GSMEM_BYTES>>>(
        ROWS_, QKVN, E_, xr, wqkvt, qkv);

    // RoPE on q and k slices; round v slice
    {
        int total_q = ROWS_ * H_ * 64;
        int total_k = ROWS_ * KVH_ * 64;
        rope_kernel<<<(total_q + 255) / 256, 256>>>(qkv, QKVN, 0, H_, total_q);
        rope_kernel<<<(total_k + 255) / 256, 256>>>(qkv, QKVN, H_ * D_, KVH_, total_k);
        vround_kernel<<<(ROWS_ * 256) / 256, 256>>>(qkv);
    }

    // Flash attention (Br=128)
    {
        int smem_bytes = FLASH_SMEM_FLOATS * (int)sizeof(float);
        cudaFuncSetAttribute(flash_attn_kernel,
                             cudaFuncAttributeMaxDynamicSharedMemorySize, smem_bytes);
        flash_attn_kernel<<<dim3(T_ / 128, H_, B_), 256, smem_bytes>>>(qkv, o);
    }

    // Output projection (o and wot both k-permuted)
    tc_gemm_kernel<<<dim3(E_ / 128, ROWS_ / 128), 256, GSMEM_BYTES>>>(
        ROWS_, E_, H_ * D_, o, wot, out);
}

// round 12
// speedup vs baseline: 1.1647x; 1.1647x over previous
#include <cuda_runtime.h>
#include <cuda_bf16.h>
#include <math.h>
#include <cstdint>

// Problem constants
#define B_  2
#define T_  2048
#define E_  2048
#define H_  16
#define KVH_ 8
#define D_  128
#define ROWS_ (B_ * T_)            // 4096
#define QKVN (H_ * D_ + 2 * KVH_ * D_)   // 4096 fused N
#define VOFF (H_ * D_ + KVH_ * D_)       // 3072: v column offset in fused buffer

// ---------------- scratch (device globals; no allocs allowed) ----------------
__device__ float g_qkv[(size_t)ROWS_ * QKVN];      // fused q|k|v
__device__ float g_o[(size_t)ROWS_ * H_ * D_];     // attn out
__device__ float g_xr[(size_t)ROWS_ * E_];         // tf32-rounded x
__device__ float g_wqkvt[(size_t)QKVN * E_];       // [wq|wk|wv]^T rows, tf32
__device__ float g_wot[(size_t)E_ * H_ * D_];

// ====================== helpers ======================
__device__ __forceinline__ uint32_t smem_u32(const void* p) {
    uint32_t a;
    asm("{ .reg .u64 t; cvta.to.shared.u64 t, %1; cvt.u32.u64 %0, t; }" : "=r"(a) : "l"(p));
    return a;
}
#define CP_ASYNC16(dst, src) \
    asm volatile("cp.async.cg.shared.global [%0], [%1], 16;" :: "r"(dst), "l"(src))
#define CP_COMMIT() asm volatile("cp.async.commit_group;" ::: "memory")
#define CP_WAIT(n)  asm volatile("cp.async.wait_group %0;" :: "n"(n) : "memory")

#define LDSM4(r0, r1, r2, r3, addr) \
    asm volatile("ldmatrix.sync.aligned.m8n8.x4.shared.b16 {%0,%1,%2,%3}, [%4];" \
        : "=r"(r0), "=r"(r1), "=r"(r2), "=r"(r3) : "r"(addr))

__device__ __forceinline__ uint32_t f2tf32(float x) {
    uint32_t u;
    asm("cvt.rna.tf32.f32 %0, %1;" : "=r"(u) : "f"(x));
    return u;
}
__device__ __forceinline__ float tf32r(float x) {
    return __uint_as_float(f2tf32(x));
}
__device__ __forceinline__ void mma_tf32(float (&c)[4], const uint32_t (&a)[4],
                                         const uint32_t (&b)[2]) {
    asm volatile(
        "mma.sync.aligned.m16n8k8.row.col.f32.tf32.tf32.f32 "
        "{%0,%1,%2,%3}, {%4,%5,%6,%7}, {%8,%9}, {%0,%1,%2,%3};"
        : "+f"(c[0]), "+f"(c[1]), "+f"(c[2]), "+f"(c[3])
        : "r"(a[0]), "r"(a[1]), "r"(a[2]), "r"(a[3]), "r"(b[0]), "r"(b[1]));
}

// ============== round x to tf32 ==============
__global__ void round_tf32_kernel(const float* __restrict__ in, float* __restrict__ out,
                                  int n4)
{
    int i = blockIdx.x * blockDim.x + threadIdx.x;
    if (i >= n4) return;
    float4 t = ((const float4*)in)[i];
    t.x = tf32r(t.x); t.y = tf32r(t.y); t.z = tf32r(t.z); t.w = tf32r(t.w);
    ((float4*)out)[i] = t;
}

// ============== round v-slice of fused qkv buffer to tf32 (in place) ==========
__global__ void vround_kernel(float* __restrict__ X)
{
    int idx = blockIdx.x * blockDim.x + threadIdx.x;
    int row = idx >> 8, c4 = idx & 255;
    float4* p = (float4*)(X + (size_t)row * QKVN + VOFF) + c4;
    float4 t = *p;
    t.x = tf32r(t.x); t.y = tf32r(t.y); t.z = tf32r(t.z); t.w = tf32r(t.w);
    *p = t;
}

// ============ fused qkv weight transpose ============
__global__ void transpose_qkv_kernel(const float* __restrict__ Wq,
                                     const float* __restrict__ Wk,
                                     const float* __restrict__ Wv,
                                     float* __restrict__ Wt)
{
    __shared__ float tile[32][33];
    int z = blockIdx.z;
    const float* W = (z == 0) ? Wq : (z == 1) ? Wk : Wv;
    int N = (z == 0) ? (H_ * D_) : (KVH_ * D_);
    int rowoff = (z == 0) ? 0 : (z == 1) ? (H_ * D_) : (H_ * D_ + KVH_ * D_);
    int bx = blockIdx.x * 32;  // n (uniform per block)
    if (bx >= N) return;
    int by = blockIdx.y * 32;  // k
    int tx = threadIdx.x, ty = threadIdx.y;
#pragma unroll
    for (int j = 0; j < 32; j += 8)
        tile[ty + j][tx] = W[(size_t)(by + ty + j) * N + bx + tx];
    __syncthreads();
#pragma unroll
    for (int j = 0; j < 32; j += 8)
        Wt[(size_t)(rowoff + bx + ty + j) * E_ + by + tx] = tf32r(tile[tx][ty + j]);
}

// ============ wo transpose: Wt[N,K] = tf32(W[K,N]) ==========
__global__ void transpose_kernel(const float* __restrict__ W, float* __restrict__ Wt,
                                 int K, int N)
{
    __shared__ float tile[32][33];
    int bx = blockIdx.x * 32;  // n
    int by = blockIdx.y * 32;  // k
    int tx = threadIdx.x, ty = threadIdx.y;
#pragma unroll
    for (int j = 0; j < 32; j += 8)
        tile[ty + j][tx] = W[(size_t)(by + ty + j) * N + bx + tx];
    __syncthreads();
#pragma unroll
    for (int j = 0; j < 32; j += 8)
        Wt[(size_t)(bx + ty + j) * K + by + tx] = tf32r(tile[tx][ty + j]);
}

// ====================== tf32 mma.sync GEMM (ldmatrix fragments) ==============
// C[M,N] = A[M,K] @ Bt[N,K]^T. CTA 128x128, BK=32, 2-stage cp.async, 2 CTAs/SM.
// Fragments loaded via ldmatrix.x4 (conflict-free with GSTRIDE=36).
#define GBM 128
#define GBN 128
#define GBK 32
#define GSTRIDE 36
#define GSTAGE_FLOATS (2 * GBM * GSTRIDE)
#define GSTAGES 2
#define GSMEM_BYTES (GSTAGES * GSTAGE_FLOATS * 4)   // 73728

__global__ void __launch_bounds__(256, 2) tc_gemm_kernel(
    int M, int N, int K,
    const float* __restrict__ A, const float* __restrict__ Bt,
    float* __restrict__ C)
{
    extern __shared__ float smf[];
    const uint32_t smem_base = smem_u32(smf);
    const int tid = threadIdx.x;
    const int wid = tid >> 5, lid = tid & 31;
    const int g = lid >> 2, tig = lid & 3;

    const int m0 = blockIdx.y * GBM;
    const int n0 = blockIdx.x * GBN;
    const float* Ab = A  + (size_t)m0 * K;
    const float* Bb = Bt + (size_t)n0 * K;
    const int nchunks = K / GBK;

    const int wm0 = (wid >> 2) * 64;
    const int wn0 = (wid & 3) * 32;

    // ldmatrix lane address components
    const int aRow = ((lid >> 3) & 1) * 8 + (lid & 7);  // tile-sel bit0 -> +8 rows
    const int aCol = (lid >> 4) * 4;                    // tile-sel bit1 -> +4 k
    const int bRow = ((lid >> 4) & 1) * 8 + (lid & 7);  // bit1 -> second nt tile
    const int bCol = ((lid >> 3) & 1) * 4;              // bit0 -> k half

    float acc[16][4];
#pragma unroll
    for (int i = 0; i < 16; i++)
#pragma unroll
        for (int jj = 0; jj < 4; jj++) acc[i][jj] = 0.f;

    auto load_chunk = [&](int j) {
        const int stage = j & 1;
        const uint32_t abase = smem_base + stage * GSTAGE_FLOATS * 4;
        const uint32_t bbase = abase + GBM * GSTRIDE * 4;
        const float* ag = Ab + j * GBK;
        const float* bg = Bb + j * GBK;
#pragma unroll
        for (int i = 0; i < 4; i++) {
            int f = i * 256 + tid;            // 0..1023
            int row = f >> 3, c = f & 7;      // c in 16B units
            uint32_t soff = (uint32_t)(row * GSTRIDE + c * 4) * 4;
            CP_ASYNC16(abase + soff, ag + (size_t)row * K + c * 4);
            CP_ASYNC16(bbase + soff, bg + (size_t)row * K + c * 4);
        }
    };

    load_chunk(0);
    CP_COMMIT();

    for (int j = 0; j < nchunks; j++) {
        CP_WAIT(0);
        __syncthreads();
        if (j + 1 < nchunks) { load_chunk(j + 1); CP_COMMIT(); }

        const uint32_t as_addr = smem_base + (uint32_t)(j & 1) * GSTAGE_FLOATS * 4;
        const uint32_t bs_addr = as_addr + GBM * GSTRIDE * 4;

#pragma unroll
        for (int ks = 0; ks < 4; ks++) {
            const int k0 = ks * 8;
            uint32_t afr[4][4], bfr[2][4];
#pragma unroll
            for (int mt = 0; mt < 4; mt++) {
                uint32_t addr = as_addr +
                    (uint32_t)((wm0 + mt * 16 + aRow) * GSTRIDE + k0 + aCol) * 4;
                LDSM4(afr[mt][0], afr[mt][1], afr[mt][2], afr[mt][3], addr);
            }
#pragma unroll
            for (int p = 0; p < 2; p++) {
                uint32_t addr = bs_addr +
                    (uint32_t)((wn0 + p * 16 + bRow) * GSTRIDE + k0 + bCol) * 4;
                LDSM4(bfr[p][0], bfr[p][1], bfr[p][2], bfr[p][3], addr);
            }
#pragma unroll
            for (int mt = 0; mt < 4; mt++)
#pragma unroll
                for (int nt = 0; nt < 4; nt++) {
                    uint32_t bb[2] = { bfr[nt >> 1][(nt & 1) * 2],
                                       bfr[nt >> 1][(nt & 1) * 2 + 1] };
                    mma_tf32(acc[mt * 4 + nt], afr[mt], bb);
                }
        }
        __syncthreads();
    }

#pragma unroll
    for (int mt = 0; mt < 4; mt++) {
#pragma unroll
        for (int nt = 0; nt < 4; nt++) {
            int row = m0 + wm0 + mt * 16 + g;
            int col = n0 + wn0 + nt * 8 + tig * 2;
            float2 lo = { acc[mt * 4 + nt][0], acc[mt * 4 + nt][1] };
            float2 hi = { acc[mt * 4 + nt][2], acc[mt * 4 + nt][3] };
            *(float2*)(C + (size_t)row * N + col) = lo;
            *(float2*)(C + (size_t)(row + 8) * N + col) = hi;
        }
    }
}

// ---------------- RoPE on a column-slice of the fused qkv buffer ------------
__global__ void rope_kernel(float* __restrict__ X, int rowstride, int coloff,
                            int nh, int total)
{
    int idx = blockIdx.x * blockDim.x + threadIdx.x;
    if (idx >= total) return;
    int j = idx & 63;
    int rest = idx >> 6;
    int hh = rest % nh;
    int row = rest / nh;
    int t = row & (T_ - 1);

    float inv = 1.0f / powf(10000.0f, (float)j * (1.0f / 64.0f));
    float ang = (float)t * inv;
    float s, c;
    sincosf(ang, &s, &c);

    float* p = X + (size_t)row * rowstride + coloff + hh * D_ + 2 * j;
    float x0 = p[0], x1 = p[1];
    p[0] = tf32r(x0 * c - x1 * s);
    p[1] = tf32r(x0 * s + x1 * c);
}

// ---------------- Flash attention (causal, GQA), Br=128, warp-private -------
#define FSTR 132
#define F_QS 0
#define F_KS (128 * FSTR)
#define F_VS (F_KS + 2 * 64 * FSTR)
#define FLASH_SMEM_FLOATS (F_VS + 2 * 64 * FSTR)   // 50688 -> 202752 B

__global__ void __launch_bounds__(256, 1) flash_attn_kernel(
    const float* __restrict__ QKV, float* __restrict__ O)
{
    extern __shared__ float sm[];
    float* Qs = sm + F_QS;
    float* Ks0 = sm + F_KS;
    float* Vs0 = sm + F_VS;
    const uint32_t smem_base = smem_u32(sm);

    const int tid = threadIdx.x;
    const int wid = tid >> 5, lid = tid & 31;
    const int g = lid >> 2, tig = lid & 3;
    const int qt = gridDim.x - 1 - blockIdx.x;
    const int h = blockIdx.y, b = blockIdx.z;
    const int kvh = h >> 1;
    const int q0 = qt * 128;
    const int wr = wid * 16;

    const float* Qg = QKV + (size_t)h * D_;
    const float* Kq = QKV + H_ * D_ + (size_t)kvh * D_;
    const float* Vq = QKV + VOFF + (size_t)kvh * D_;

    auto prefetch_kv = [&](int kt) {
        const int stage = kt & 1;
        const uint32_t kb = smem_base + (uint32_t)(F_KS + stage * 64 * FSTR) * 4;
        const uint32_t vb = smem_base + (uint32_t)(F_VS + stage * 64 * FSTR) * 4;
#pragma unroll
        for (int i = 0; i < 8; i++) {
            int f = i * 256 + tid;
            int row = f >> 5, c16 = f & 31;
            size_t goff = (size_t)(b * T_ + kt * 64 + row) * QKVN + c16 * 4;
            uint32_t soff = (uint32_t)(row * FSTR + c16 * 4) * 4;
            CP_ASYNC16(kb + soff, Kq + goff);
            CP_ASYNC16(vb + soff, Vq + goff);
        }
    };

    {
#pragma unroll
        for (int i = 0; i < 16; i++) {
            int f = i * 256 + tid;
            int row = f >> 5, c = f & 31;
            const float4* src = (const float4*)(Qg + (size_t)(b * T_ + q0 + row) * QKVN) + c;
            *((float4*)(Qs + row * FSTR) + c) = *src;
        }
    }

    prefetch_kv(0);
    CP_COMMIT();

    float oacc[16][4];
#pragma unroll
    for (int i = 0; i < 16; i++)
#pragma unroll
        for (int jj = 0; jj < 4; jj++) oacc[i][jj] = 0.f;
    float m0 = -INFINITY, m1 = -INFINITY, l0 = 0.f, l1 = 0.f;

    const float scale = 0.08838834764831845f;
    const int last = 2 * qt + 1;
    const int srcA = (lid & ~3) | (tig >> 1);
    const int srcB = (lid & ~3) | (2 + (tig >> 1));
    const bool selb = (tig & 1);

    for (int kt = 0; kt <= last; kt++) {
        CP_WAIT(0);
        __syncthreads();
        if (kt < last) { prefetch_kv(kt + 1); CP_COMMIT(); }

        const float* ks = Ks0 + (kt & 1) * 64 * FSTR;
        const float* vs = Vs0 + (kt & 1) * 64 * FSTR;

        float sacc[8][4];
#pragma unroll
        for (int nt = 0; nt < 8; nt++)
#pragma unroll
            for (int jj = 0; jj < 4; jj++) sacc[nt][jj] = 0.f;

#pragma unroll
        for (int ksi = 0; ksi < 16; ksi++) {
            const int k0 = ksi * 8;
            uint32_t a[4];
            const uint32_t* ap = (const uint32_t*)(Qs + (wr + g) * FSTR + k0 + tig);
            a[0] = ap[0];
            a[1] = ap[8 * FSTR];
            a[2] = ap[4];
            a[3] = ap[8 * FSTR + 4];
#pragma unroll
            for (int nt = 0; nt < 8; nt++) {
                uint32_t bb[2];
                const uint32_t* bp = (const uint32_t*)(ks + (nt * 8 + g) * FSTR + k0 + tig);
                bb[0] = bp[0];
                bb[1] = bp[4];
                mma_tf32(sacc[nt], a, bb);
            }
        }

        {
            const int r0 = wr + g, r1 = wr + g + 8;
            const int koff = (kt - 2 * qt) * 64;
            const bool diag = (kt >= 2 * qt);
#pragma unroll
            for (int nt = 0; nt < 8; nt++) {
                int j0 = nt * 8 + 2 * tig;
                sacc[nt][0] *= scale;
                sacc[nt][1] *= scale;
                sacc[nt][2] *= scale;
                sacc[nt][3] *= scale;
                if (diag) {
                    if (koff + j0     > r0) sacc[nt][0] = -1e30f;
                    if (koff + j0 + 1 > r0) sacc[nt][1] = -1e30f;
                    if (koff + j0     > r1) sacc[nt][2] = -1e30f;
                    if (koff + j0 + 1 > r1) sacc[nt][3] = -1e30f;
                }
            }
        }

        {
            float mx0 = -INFINITY, mx1 = -INFINITY;
#pragma unroll
            for (int nt = 0; nt < 8; nt++) {
                mx0 = fmaxf(mx0, fmaxf(sacc[nt][0], sacc[nt][1]));
                mx1 = fmaxf(mx1, fmaxf(sacc[nt][2], sacc[nt][3]));
            }
            mx0 = fmaxf(mx0, __shfl_xor_sync(0xFFFFFFFF, mx0, 1));
            mx0 = fmaxf(mx0, __shfl_xor_sync(0xFFFFFFFF, mx0, 2));
            mx1 = fmaxf(mx1, __shfl_xor_sync(0xFFFFFFFF, mx1, 1));
            mx1 = fmaxf(mx1, __shfl_xor_sync(0xFFFFFFFF, mx1, 2));
            mx0 = fmaxf(mx0, m0);
            mx1 = fmaxf(mx1, m1);
            float sum0 = 0.f, sum1 = 0.f;
#pragma unroll
            for (int nt = 0; nt < 8; nt++) {
                float p0 = tf32r(__expf(sacc[nt][0] - mx0));
                float p1 = tf32r(__expf(sacc[nt][1] - mx0));
                float p2 = tf32r(__expf(sacc[nt][2] - mx1));
                float p3 = tf32r(__expf(sacc[nt][3] - mx1));
                sacc[nt][0] = p0; sacc[nt][1] = p1;
                sacc[nt][2] = p2; sacc[nt][3] = p3;
                sum0 += p0 + p1;
                sum1 += p2 + p3;
            }
            sum0 += __shfl_xor_sync(0xFFFFFFFF, sum0, 1);
            sum0 += __shfl_xor_sync(0xFFFFFFFF, sum0, 2);
            sum1 += __shfl_xor_sync(0xFFFFFFFF, sum1, 1);
            sum1 += __shfl_xor_sync(0xFFFFFFFF, sum1, 2);
            float al0 = __expf(m0 - mx0);
            float al1 = __expf(m1 - mx1);
            l0 = l0 * al0 + sum0;
            l1 = l1 * al1 + sum1;
            m0 = mx0; m1 = mx1;
#pragma unroll
            for (int nt = 0; nt < 16; nt++) {
                oacc[nt][0] *= al0; oacc[nt][1] *= al0;
                oacc[nt][2] *= al1; oacc[nt][3] *= al1;
            }
        }

#pragma unroll
        for (int ksi = 0; ksi < 8; ksi++) {
            const int k0 = ksi * 8;
            uint32_t a[4];
            {
                float v00 = __shfl_sync(0xFFFFFFFF, sacc[ksi][0], srcA);
                float v01 = __shfl_sync(0xFFFFFFFF, sacc[ksi][1], srcA);
                float v10 = __shfl_sync(0xFFFFFFFF, sacc[ksi][2], srcA);
                float v11 = __shfl_sync(0xFFFFFFFF, sacc[ksi][3], srcA);
                float w00 = __shfl_sync(0xFFFFFFFF, sacc[ksi][0], srcB);
                float w01 = __shfl_sync(0xFFFFFFFF, sacc[ksi][1], srcB);
                float w10 = __shfl_sync(0xFFFFFFFF, sacc[ksi][2], srcB);
                float w11 = __shfl_sync(0xFFFFFFFF, sacc[ksi][3], srcB);
                a[0] = __float_as_uint(selb ? v01 : v00);
                a[1] = __float_as_uint(selb ? v11 : v10);
                a[2] = __float_as_uint(selb ? w01 : w00);
                a[3] = __float_as_uint(selb ? w11 : w10);
            }
            const uint32_t* vp = (const uint32_t*)(vs + (k0 + tig) * FSTR);
#pragma unroll
            for (int nt = 0; nt < 16; nt++) {
                int col = nt * 8 + g;
                uint32_t bb[2];
                bb[0] = vp[col];
                bb[1] = vp[4 * FSTR + col];
                mma_tf32(oacc[nt], a, bb);
            }
        }
    }

    {
        float il0 = 1.f / l0;
        float il1 = 1.f / l1;
        float* O0 = O + (size_t)(b * T_ + q0 + wr + g) * (H_ * D_) + h * D_;
        float* O1 = O + (size_t)(b * T_ + q0 + wr + g + 8) * (H_ * D_) + h * D_;
#pragma unroll
        for (int nt = 0; nt < 16; nt++) {
            int col = nt * 8 + 2 * tig;
            *(float2*)(O0 + col) = make_float2(tf32r(oacc[nt][0] * il0), tf32r(oacc[nt][1] * il0));
            *(float2*)(O1 + col) = make_float2(tf32r(oacc[nt][2] * il1), tf32r(oacc[nt][3] * il1));
        }
    }
}

// -------------------------------- launch -------------------------------------
extern "C" void kernel_launch(void* const* d_in, const int* in_sizes, int n_in,
                              void* d_out, int out_size)
{
    const float* x  = (const float*)d_in[0];
    const float* wq = (const float*)d_in[2];
    const float* wk = (const float*)d_in[3];
    const float* wv = (const float*)d_in[4];
    const float* wo = (const float*)d_in[5];
    float* out = (float*)d_out;

    float *qkv, *o, *xr, *wqkvt, *wot;
    cudaGetSymbolAddress((void**)&qkv, g_qkv);
    cudaGetSymbolAddress((void**)&o, g_o);
    cudaGetSymbolAddress((void**)&xr, g_xr);
    cudaGetSymbolAddress((void**)&wqkvt, g_wqkvt);
    cudaGetSymbolAddress((void**)&wot, g_wot);

    dim3 tb(32, 8);
    // launch 0: round x
    round_tf32_kernel<<<(ROWS_ * E_ / 4 + 255) / 256, 256>>>(x, xr, ROWS_ * E_ / 4);
    // launch 1: fused qkv weight transpose
    transpose_qkv_kernel<<<dim3(64, 64, 3), tb>>>(wq, wk, wv, wqkvt);
    // launch 2: wo transpose
    transpose_kernel<<<dim3(E_ / 32, (H_ * D_) / 32), tb>>>(wo, wot, H_ * D_, E_);

    cudaFuncSetAttribute(tc_gemm_kernel,
                         cudaFuncAttributeMaxDynamicSharedMemorySize, GSMEM_BYTES);

    // launch 3 (ncu-captured): fused QKV projection
    tc_gemm_kernel<<<dim3(QKVN / 128, ROWS_ / 128), 256, GSMEM_BYTES>>>(
        ROWS_, QKVN, E_, xr, wqkvt, qkv);

    // RoPE on q and k slices; round v slice
    {
        int total_q = ROWS_ * H_ * 64;
        int total_k = ROWS_ * KVH_ * 64;
        rope_kernel<<<(total_q + 255) / 256, 256>>>(qkv, QKVN, 0, H_, total_q);
        rope_kernel<<<(total_k + 255) / 256, 256>>>(qkv, QKVN, H_ * D_, KVH_, total_k);
        vround_kernel<<<(ROWS_ * 256) / 256, 256>>>(qkv);
    }

    // Flash attention (Br=128)
    {
        int smem_bytes = FLASH_SMEM_FLOATS * (int)sizeof(float);
        cudaFuncSetAttribute(flash_attn_kernel,
                             cudaFuncAttributeMaxDynamicSharedMemorySize, smem_bytes);
        flash_attn_kernel<<<dim3(T_ / 128, H_, B_), 256, smem_bytes>>>(qkv, o);
    }

    // Output projection
    tc_gemm_kernel<<<dim3(E_ / 128, ROWS_ / 128), 256, GSMEM_BYTES>>>(
        ROWS_, E_, H_ * D_, o, wot, out);
}

// round 14
// speedup vs baseline: 1.1799x; 1.0130x over previous
#include <cuda_runtime.h>
#include <cuda_bf16.h>
#include <math.h>
#include <cstdint>

// Problem constants
#define B_  2
#define T_  2048
#define E_  2048
#define H_  16
#define KVH_ 8
#define D_  128
#define ROWS_ (B_ * T_)            // 4096
#define QKVN (H_ * D_ + 2 * KVH_ * D_)   // 4096 fused N
#define VOFF (H_ * D_ + KVH_ * D_)       // 3072: v column offset in fused buffer

// ---------------- scratch (device globals; no allocs allowed) ----------------
__device__ float g_qkv[(size_t)ROWS_ * QKVN];      // fused q|k|v
__device__ float g_o[(size_t)ROWS_ * H_ * D_];     // attn out
__device__ float g_xr[(size_t)ROWS_ * E_];         // tf32-rounded x
__device__ float g_wqkvt[(size_t)QKVN * E_];       // [wq|wk|wv]^T rows, tf32
__device__ float g_wot[(size_t)E_ * H_ * D_];

// ====================== helpers ======================
__device__ __forceinline__ uint32_t smem_u32(const void* p) {
    uint32_t a;
    asm("{ .reg .u64 t; cvta.to.shared.u64 t, %1; cvt.u32.u64 %0, t; }" : "=r"(a) : "l"(p));
    return a;
}
#define CP_ASYNC16(dst, src) \
    asm volatile("cp.async.cg.shared.global [%0], [%1], 16;" :: "r"(dst), "l"(src))
#define CP_COMMIT() asm volatile("cp.async.commit_group;" ::: "memory")
#define CP_WAIT(n)  asm volatile("cp.async.wait_group %0;" :: "n"(n) : "memory")

#define LDSM4(r0, r1, r2, r3, addr) \
    asm volatile("ldmatrix.sync.aligned.m8n8.x4.shared.b16 {%0,%1,%2,%3}, [%4];" \
        : "=r"(r0), "=r"(r1), "=r"(r2), "=r"(r3) : "r"(addr))

__device__ __forceinline__ uint32_t f2tf32(float x) {
    uint32_t u;
    asm("cvt.rna.tf32.f32 %0, %1;" : "=r"(u) : "f"(x));
    return u;
}
__device__ __forceinline__ float tf32r(float x) {
    return __uint_as_float(f2tf32(x));
}
__device__ __forceinline__ void mma_tf32(float (&c)[4], const uint32_t (&a)[4],
                                         const uint32_t (&b)[2]) {
    asm volatile(
        "mma.sync.aligned.m16n8k8.row.col.f32.tf32.tf32.f32 "
        "{%0,%1,%2,%3}, {%4,%5,%6,%7}, {%8,%9}, {%0,%1,%2,%3};"
        : "+f"(c[0]), "+f"(c[1]), "+f"(c[2]), "+f"(c[3])
        : "r"(a[0]), "r"(a[1]), "r"(a[2]), "r"(a[3]), "r"(b[0]), "r"(b[1]));
}

// ============== round x to tf32 ==============
__global__ void round_tf32_kernel(const float* __restrict__ in, float* __restrict__ out,
                                  int n4)
{
    int i = blockIdx.x * blockDim.x + threadIdx.x;
    if (i >= n4) return;
    float4 t = ((const float4*)in)[i];
    t.x = tf32r(t.x); t.y = tf32r(t.y); t.z = tf32r(t.z); t.w = tf32r(t.w);
    ((float4*)out)[i] = t;
}

// ============== round v-slice of fused qkv buffer to tf32 (in place) ==========
__global__ void vround_kernel(float* __restrict__ X)
{
    int idx = blockIdx.x * blockDim.x + threadIdx.x;
    int row = idx >> 8, c4 = idx & 255;
    float4* p = (float4*)(X + (size_t)row * QKVN + VOFF) + c4;
    float4 t = *p;
    t.x = tf32r(t.x); t.y = tf32r(t.y); t.z = tf32r(t.z); t.w = tf32r(t.w);
    *p = t;
}

// ============ fused qkv weight transpose ============
__global__ void transpose_qkv_kernel(const float* __restrict__ Wq,
                                     const float* __restrict__ Wk,
                                     const float* __restrict__ Wv,
                                     float* __restrict__ Wt)
{
    __shared__ float tile[32][33];
    int z = blockIdx.z;
    const float* W = (z == 0) ? Wq : (z == 1) ? Wk : Wv;
    int N = (z == 0) ? (H_ * D_) : (KVH_ * D_);
    int rowoff = (z == 0) ? 0 : (z == 1) ? (H_ * D_) : (H_ * D_ + KVH_ * D_);
    int bx = blockIdx.x * 32;  // n (uniform per block)
    if (bx >= N) return;
    int by = blockIdx.y * 32;  // k
    int tx = threadIdx.x, ty = threadIdx.y;
#pragma unroll
    for (int j = 0; j < 32; j += 8)
        tile[ty + j][tx] = W[(size_t)(by + ty + j) * N + bx + tx];
    __syncthreads();
#pragma unroll
    for (int j = 0; j < 32; j += 8)
        Wt[(size_t)(rowoff + bx + ty + j) * E_ + by + tx] = tf32r(tile[tx][ty + j]);
}

// ============ wo transpose: Wt[N,K] = tf32(W[K,N]) ==========
__global__ void transpose_kernel(const float* __restrict__ W, float* __restrict__ Wt,
                                 int K, int N)
{
    __shared__ float tile[32][33];
    int bx = blockIdx.x * 32;  // n
    int by = blockIdx.y * 32;  // k
    int tx = threadIdx.x, ty = threadIdx.y;
#pragma unroll
    for (int j = 0; j < 32; j += 8)
        tile[ty + j][tx] = W[(size_t)(by + ty + j) * N + bx + tx];
    __syncthreads();
#pragma unroll
    for (int j = 0; j < 32; j += 8)
        Wt[(size_t)(bx + ty + j) * K + by + tx] = tf32r(tile[tx][ty + j]);
}

// ====================== tf32 mma.sync GEMM (ldmatrix + 3-stage) ==============
// C[M,N] = A[M,K] @ Bt[N,K]^T. CTA 128x128, BK=32, 3-stage cp.async, 2 CTAs/SM.
#define GBM 128
#define GBN 128
#define GBK 32
#define GSTRIDE 36
#define GSTAGE_FLOATS (2 * GBM * GSTRIDE)
#define GSTAGES 3
#define GSMEM_BYTES (GSTAGES * GSTAGE_FLOATS * 4)   // 110592

__global__ void __launch_bounds__(256, 2) tc_gemm_kernel(
    int M, int N, int K,
    const float* __restrict__ A, const float* __restrict__ Bt,
    float* __restrict__ C)
{
    extern __shared__ float smf[];
    const uint32_t smem_base = smem_u32(smf);
    const int tid = threadIdx.x;
    const int wid = tid >> 5, lid = tid & 31;
    const int g = lid >> 2, tig = lid & 3;

    const int m0 = blockIdx.y * GBM;
    const int n0 = blockIdx.x * GBN;
    const float* Ab = A  + (size_t)m0 * K;
    const float* Bb = Bt + (size_t)n0 * K;
    const int nchunks = K / GBK;

    const int wm0 = (wid >> 2) * 64;
    const int wn0 = (wid & 3) * 32;

    // ldmatrix lane address components
    const int aRow = ((lid >> 3) & 1) * 8 + (lid & 7);
    const int aCol = (lid >> 4) * 4;
    const int bRow = ((lid >> 4) & 1) * 8 + (lid & 7);
    const int bCol = ((lid >> 3) & 1) * 4;

    float acc[16][4];
#pragma unroll
    for (int i = 0; i < 16; i++)
#pragma unroll
        for (int jj = 0; jj < 4; jj++) acc[i][jj] = 0.f;

    auto load_chunk = [&](int j) {
        const int stage = j % GSTAGES;
        const uint32_t abase = smem_base + stage * GSTAGE_FLOATS * 4;
        const uint32_t bbase = abase + GBM * GSTRIDE * 4;
        const float* ag = Ab + j * GBK;
        const float* bg = Bb + j * GBK;
#pragma unroll
        for (int i = 0; i < 4; i++) {
            int f = i * 256 + tid;
            int row = f >> 3, c = f & 7;
            uint32_t soff = (uint32_t)(row * GSTRIDE + c * 4) * 4;
            CP_ASYNC16(abase + soff, ag + (size_t)row * K + c * 4);
            CP_ASYNC16(bbase + soff, bg + (size_t)row * K + c * 4);
        }
    };

    load_chunk(0); CP_COMMIT();
    load_chunk(1); CP_COMMIT();

    for (int j = 0; j < nchunks; j++) {
        CP_WAIT(1);                  // chunk j resident (j+1 may be in flight)
        __syncthreads();
        if (j + 2 < nchunks) { load_chunk(j + 2); CP_COMMIT(); }

        const uint32_t as_addr = smem_base + (uint32_t)(j % GSTAGES) * GSTAGE_FLOATS * 4;
        const uint32_t bs_addr = as_addr + GBM * GSTRIDE * 4;

#pragma unroll
        for (int ks = 0; ks < 4; ks++) {
            const int k0 = ks * 8;
            uint32_t afr[4][4], bfr[2][4];
#pragma unroll
            for (int mt = 0; mt < 4; mt++) {
                uint32_t addr = as_addr +
                    (uint32_t)((wm0 + mt * 16 + aRow) * GSTRIDE + k0 + aCol) * 4;
                LDSM4(afr[mt][0], afr[mt][1], afr[mt][2], afr[mt][3], addr);
            }
#pragma unroll
            for (int p = 0; p < 2; p++) {
                uint32_t addr = bs_addr +
                    (uint32_t)((wn0 + p * 16 + bRow) * GSTRIDE + k0 + bCol) * 4;
                LDSM4(bfr[p][0], bfr[p][1], bfr[p][2], bfr[p][3], addr);
            }
#pragma unroll
            for (int mt = 0; mt < 4; mt++)
#pragma unroll
                for (int nt = 0; nt < 4; nt++) {
                    uint32_t bb[2] = { bfr[nt >> 1][(nt & 1) * 2],
                                       bfr[nt >> 1][(nt & 1) * 2 + 1] };
                    mma_tf32(acc[mt * 4 + nt], afr[mt], bb);
                }
        }
        __syncthreads();
    }

#pragma unroll
    for (int mt = 0; mt < 4; mt++) {
#pragma unroll
        for (int nt = 0; nt < 4; nt++) {
            int row = m0 + wm0 + mt * 16 + g;
            int col = n0 + wn0 + nt * 8 + tig * 2;
            float2 lo = { acc[mt * 4 + nt][0], acc[mt * 4 + nt][1] };
            float2 hi = { acc[mt * 4 + nt][2], acc[mt * 4 + nt][3] };
            *(float2*)(C + (size_t)row * N + col) = lo;
            *(float2*)(C + (size_t)(row + 8) * N + col) = hi;
        }
    }
}

// ---------------- RoPE on a column-slice of the fused qkv buffer ------------
__global__ void rope_kernel(float* __restrict__ X, int rowstride, int coloff,
                            int nh, int total)
{
    int idx = blockIdx.x * blockDim.x + threadIdx.x;
    if (idx >= total) return;
    int j = idx & 63;
    int rest = idx >> 6;
    int hh = rest % nh;
    int row = rest / nh;
    int t = row & (T_ - 1);

    float inv = 1.0f / powf(10000.0f, (float)j * (1.0f / 64.0f));
    float ang = (float)t * inv;
    float s, c;
    sincosf(ang, &s, &c);

    float* p = X + (size_t)row * rowstride + coloff + hh * D_ + 2 * j;
    float x0 = p[0], x1 = p[1];
    p[0] = tf32r(x0 * c - x1 * s);
    p[1] = tf32r(x0 * s + x1 * c);
}

// ---------------- Flash attention (causal, GQA), Br=128, warp-private -------
// QK^T fragments via ldmatrix (FSTR=132 conflict-free); V stays scalar LDS.
#define FSTR 132
#define F_QS 0
#define F_KS (128 * FSTR)
#define F_VS (F_KS + 2 * 64 * FSTR)
#define FLASH_SMEM_FLOATS (F_VS + 2 * 64 * FSTR)   // 50688 -> 202752 B

__global__ void __launch_bounds__(256, 1) flash_attn_kernel(
    const float* __restrict__ QKV, float* __restrict__ O)
{
    extern __shared__ float sm[];
    float* Qs = sm + F_QS;
    float* Vs0 = sm + F_VS;
    const uint32_t smem_base = smem_u32(sm);
    const uint32_t Qs_addr = smem_base;
    const uint32_t Ks_addr = smem_base + (uint32_t)F_KS * 4;

    const int tid = threadIdx.x;
    const int wid = tid >> 5, lid = tid & 31;
    const int g = lid >> 2, tig = lid & 3;
    const int qt = gridDim.x - 1 - blockIdx.x;
    const int h = blockIdx.y, b = blockIdx.z;
    const int kvh = h >> 1;
    const int q0 = qt * 128;
    const int wr = wid * 16;

    const float* Qg = QKV + (size_t)h * D_;
    const float* Kq = QKV + H_ * D_ + (size_t)kvh * D_;
    const float* Vq = QKV + VOFF + (size_t)kvh * D_;

    // ldmatrix lane address components (same mapping as GEMM)
    const int aRow = ((lid >> 3) & 1) * 8 + (lid & 7);
    const int aCol = (lid >> 4) * 4;
    const int bRow = ((lid >> 4) & 1) * 8 + (lid & 7);
    const int bCol = ((lid >> 3) & 1) * 4;

    auto prefetch_kv = [&](int kt) {
        const int stage = kt & 1;
        const uint32_t kb = smem_base + (uint32_t)(F_KS + stage * 64 * FSTR) * 4;
        const uint32_t vb = smem_base + (uint32_t)(F_VS + stage * 64 * FSTR) * 4;
#pragma unroll
        for (int i = 0; i < 8; i++) {
            int f = i * 256 + tid;
            int row = f >> 5, c16 = f & 31;
            size_t goff = (size_t)(b * T_ + kt * 64 + row) * QKVN + c16 * 4;
            uint32_t soff = (uint32_t)(row * FSTR + c16 * 4) * 4;
            CP_ASYNC16(kb + soff, Kq + goff);
            CP_ASYNC16(vb + soff, Vq + goff);
        }
    };

    {
#pragma unroll
        for (int i = 0; i < 16; i++) {
            int f = i * 256 + tid;
            int row = f >> 5, c = f & 31;
            const float4* src = (const float4*)(Qg + (size_t)(b * T_ + q0 + row) * QKVN) + c;
            *((float4*)(Qs + row * FSTR) + c) = *src;
        }
    }

    prefetch_kv(0);
    CP_COMMIT();

    float oacc[16][4];
#pragma unroll
    for (int i = 0; i < 16; i++)
#pragma unroll
        for (int jj = 0; jj < 4; jj++) oacc[i][jj] = 0.f;
    float m0 = -INFINITY, m1 = -INFINITY, l0 = 0.f, l1 = 0.f;

    const float scale = 0.08838834764831845f;
    const int last = 2 * qt + 1;
    const int srcA = (lid & ~3) | (tig >> 1);
    const int srcB = (lid & ~3) | (2 + (tig >> 1));
    const bool selb = (tig & 1);

    for (int kt = 0; kt <= last; kt++) {
        CP_WAIT(0);
        __syncthreads();
        if (kt < last) { prefetch_kv(kt + 1); CP_COMMIT(); }

        const uint32_t ks_addr = Ks_addr + (uint32_t)(kt & 1) * 64 * FSTR * 4;
        const float* vs = Vs0 + (kt & 1) * 64 * FSTR;

        // ---- QK^T: warp tile 16x64, K=128 in 16 ksteps, ldmatrix fragments
        float sacc[8][4];
#pragma unroll
        for (int nt = 0; nt < 8; nt++)
#pragma unroll
            for (int jj = 0; jj < 4; jj++) sacc[nt][jj] = 0.f;

#pragma unroll
        for (int ksi = 0; ksi < 16; ksi++) {
            const int k0 = ksi * 8;
            uint32_t a[4], bfr[4][4];
            {
                uint32_t addr = Qs_addr + (uint32_t)((wr + aRow) * FSTR + k0 + aCol) * 4;
                LDSM4(a[0], a[1], a[2], a[3], addr);
            }
#pragma unroll
            for (int p = 0; p < 4; p++) {
                uint32_t addr = ks_addr + (uint32_t)((p * 16 + bRow) * FSTR + k0 + bCol) * 4;
                LDSM4(bfr[p][0], bfr[p][1], bfr[p][2], bfr[p][3], addr);
            }
#pragma unroll
            for (int nt = 0; nt < 8; nt++) {
                uint32_t bb[2] = { bfr[nt >> 1][(nt & 1) * 2],
                                   bfr[nt >> 1][(nt & 1) * 2 + 1] };
                mma_tf32(sacc[nt], a, bb);
            }
        }

        {
            const int r0 = wr + g, r1 = wr + g + 8;
            const int koff = (kt - 2 * qt) * 64;
            const bool diag = (kt >= 2 * qt);
#pragma unroll
            for (int nt = 0; nt < 8; nt++) {
                int j0 = nt * 8 + 2 * tig;
                sacc[nt][0] *= scale;
                sacc[nt][1] *= scale;
                sacc[nt][2] *= scale;
                sacc[nt][3] *= scale;
                if (diag) {
                    if (koff + j0     > r0) sacc[nt][0] = -1e30f;
                    if (koff + j0 + 1 > r0) sacc[nt][1] = -1e30f;
                    if (koff + j0     > r1) sacc[nt][2] = -1e30f;
                    if (koff + j0 + 1 > r1) sacc[nt][3] = -1e30f;
                }
            }
        }

        {
            float mx0 = -INFINITY, mx1 = -INFINITY;
#pragma unroll
            for (int nt = 0; nt < 8; nt++) {
                mx0 = fmaxf(mx0, fmaxf(sacc[nt][0], sacc[nt][1]));
                mx1 = fmaxf(mx1, fmaxf(sacc[nt][2], sacc[nt][3]));
            }
            mx0 = fmaxf(mx0, __shfl_xor_sync(0xFFFFFFFF, mx0, 1));
            mx0 = fmaxf(mx0, __shfl_xor_sync(0xFFFFFFFF, mx0, 2));
            mx1 = fmaxf(mx1, __shfl_xor_sync(0xFFFFFFFF, mx1, 1));
            mx1 = fmaxf(mx1, __shfl_xor_sync(0xFFFFFFFF, mx1, 2));
            mx0 = fmaxf(mx0, m0);
            mx1 = fmaxf(mx1, m1);
            float sum0 = 0.f, sum1 = 0.f;
#pragma unroll
            for (int nt = 0; nt < 8; nt++) {
                float p0 = tf32r(__expf(sacc[nt][0] - mx0));
                float p1 = tf32r(__expf(sacc[nt][1] - mx0));
                float p2 = tf32r(__expf(sacc[nt][2] - mx1));
                float p3 = tf32r(__expf(sacc[nt][3] - mx1));
                sacc[nt][0] = p0; sacc[nt][1] = p1;
                sacc[nt][2] = p2; sacc[nt][3] = p3;
                sum0 += p0 + p1;
                sum1 += p2 + p3;
            }
            sum0 += __shfl_xor_sync(0xFFFFFFFF, sum0, 1);
            sum0 += __shfl_xor_sync(0xFFFFFFFF, sum0, 2);
            sum1 += __shfl_xor_sync(0xFFFFFFFF, sum1, 1);
            sum1 += __shfl_xor_sync(0xFFFFFFFF, sum1, 2);
            float al0 = __expf(m0 - mx0);
            float al1 = __expf(m1 - mx1);
            l0 = l0 * al0 + sum0;
            l1 = l1 * al1 + sum1;
            m0 = mx0; m1 = mx1;
#pragma unroll
            for (int nt = 0; nt < 16; nt++) {
                oacc[nt][0] *= al0; oacc[nt][1] *= al0;
                oacc[nt][2] *= al1; oacc[nt][3] *= al1;
            }
        }

#pragma unroll
        for (int ksi = 0; ksi < 8; ksi++) {
            const int k0 = ksi * 8;
            uint32_t a[4];
            {
                float v00 = __shfl_sync(0xFFFFFFFF, sacc[ksi][0], srcA);
                float v01 = __shfl_sync(0xFFFFFFFF, sacc[ksi][1], srcA);
                float v10 = __shfl_sync(0xFFFFFFFF, sacc[ksi][2], srcA);
                float v11 = __shfl_sync(0xFFFFFFFF, sacc[ksi][3], srcA);
                float w00 = __shfl_sync(0xFFFFFFFF, sacc[ksi][0], srcB);
                float w01 = __shfl_sync(0xFFFFFFFF, sacc[ksi][1], srcB);
                float w10 = __shfl_sync(0xFFFFFFFF, sacc[ksi][2], srcB);
                float w11 = __shfl_sync(0xFFFFFFFF, sacc[ksi][3], srcB);
                a[0] = __float_as_uint(selb ? v01 : v00);
                a[1] = __float_as_uint(selb ? v11 : v10);
                a[2] = __float_as_uint(selb ? w01 : w00);
                a[3] = __float_as_uint(selb ? w11 : w10);
            }
            const uint32_t* vp = (const uint32_t*)(vs + (k0 + tig) * FSTR);
#pragma unroll
            for (int nt = 0; nt < 16; nt++) {
                int col = nt * 8 + g;
                uint32_t bb[2];
                bb[0] = vp[col];
                bb[1] = vp[4 * FSTR + col];
                mma_tf32(oacc[nt], a, bb);
            }
        }
    }

    {
        float il0 = 1.f / l0;
        float il1 = 1.f / l1;
        float* O0 = O + (size_t)(b * T_ + q0 + wr + g) * (H_ * D_) + h * D_;
        float* O1 = O + (size_t)(b * T_ + q0 + wr + g + 8) * (H_ * D_) + h * D_;
#pragma unroll
        for (int nt = 0; nt < 16; nt++) {
            int col = nt * 8 + 2 * tig;
            *(float2*)(O0 + col) = make_float2(tf32r(oacc[nt][0] * il0), tf32r(oacc[nt][1] * il0));
            *(float2*)(O1 + col) = make_float2(tf32r(oacc[nt][2] * il1), tf32r(oacc[nt][3] * il1));
        }
    }
}

// -------------------------------- launch -------------------------------------
extern "C" void kernel_launch(void* const* d_in, const int* in_sizes, int n_in,
                              void* d_out, int out_size)
{
    const float* x  = (const float*)d_in[0];
    const float* wq = (const float*)d_in[2];
    const float* wk = (const float*)d_in[3];
    const float* wv = (const float*)d_in[4];
    const float* wo = (const float*)d_in[5];
    float* out = (float*)d_out;

    float *qkv, *o, *xr, *wqkvt, *wot;
    cudaGetSymbolAddress((void**)&qkv, g_qkv);
    cudaGetSymbolAddress((void**)&o, g_o);
    cudaGetSymbolAddress((void**)&xr, g_xr);
    cudaGetSymbolAddress((void**)&wqkvt, g_wqkvt);
    cudaGetSymbolAddress((void**)&wot, g_wot);

    dim3 tb(32, 8);
    // launch 0: round x
    round_tf32_kernel<<<(ROWS_ * E_ / 4 + 255) / 256, 256>>>(x, xr, ROWS_ * E_ / 4);
    // launch 1: fused qkv weight transpose
    transpose_qkv_kernel<<<dim3(64, 64, 3), tb>>>(wq, wk, wv, wqkvt);
    // launch 2: wo transpose
    transpose_kernel<<<dim3(E_ / 32, (H_ * D_) / 32), tb>>>(wo, wot, H_ * D_, E_);

    cudaFuncSetAttribute(tc_gemm_kernel,
                         cudaFuncAttributeMaxDynamicSharedMemorySize, GSMEM_BYTES);

    // launch 3 (ncu-captured): fused QKV projection
    tc_gemm_kernel<<<dim3(QKVN / 128, ROWS_ / 128), 256, GSMEM_BYTES>>>(
        ROWS_, QKVN, E_, xr, wqkvt, qkv);

    // RoPE on q and k slices; round v slice
    {
        int total_q = ROWS_ * H_ * 64;
        int total_k = ROWS_ * KVH_ * 64;
        rope_kernel<<<(total_q + 255) / 256, 256>>>(qkv, QKVN, 0, H_, total_q);
        rope_kernel<<<(total_k + 255) / 256, 256>>>(qkv, QKVN, H_ * D_, KVH_, total_k);
        vround_kernel<<<(ROWS_ * 256) / 256, 256>>>(qkv);
    }

    // Flash attention (Br=128)
    {
        int smem_bytes = FLASH_SMEM_FLOATS * (int)sizeof(float);
        cudaFuncSetAttribute(flash_attn_kernel,
                             cudaFuncAttributeMaxDynamicSharedMemorySize, smem_bytes);
        flash_attn_kernel<<<dim3(T_ / 128, H_, B_), 256, smem_bytes>>>(qkv, o);
    }

    // Output projection
    tc_gemm_kernel<<<dim3(E_ / 128, ROWS_ / 128), 256, GSMEM_BYTES>>>(
        ROWS_, E_, H_ * D_, o, wot, out);
}